// round 1
// baseline (speedup 1.0000x reference)
#include <cuda_runtime.h>

#define EMBED 1024
#define NHEAD 16
#define HDIM  64
#define BATCH 4
#define SEQ   2048
#define MTOT  (BATCH*SEQ)      /* 8192 */
#define QKVF  (3*EMBED)        /* 3072 */

// Scratch (device globals: allocation-free per harness rules)
__device__ float g_qkv[(size_t)MTOT * QKVF];   // [M, 3C]
__device__ float g_att[(size_t)MTOT * EMBED];  // [M, C]

// ---------------------------------------------------------------------------
// SGEMM: C[M,N] = A[M,K] @ B[N,K]^T + bias[N]   (both A and B are K-major)
// 128x128 block tile, BK=8, 256 threads, 8x8 microtile per thread.
// ---------------------------------------------------------------------------
__global__ __launch_bounds__(256) void sgemm_bias(
    const float* __restrict__ A, const float* __restrict__ Bm,
    const float* __restrict__ bias, float* __restrict__ C,
    int M, int N, int K)
{
  __shared__ float As[8][128];
  __shared__ float Bs[8][128];

  const int tid = threadIdx.x;
  const int tx  = tid & 15;        // 0..15 -> N microtiles
  const int ty  = tid >> 4;        // 0..15 -> M microtiles
  const int m0  = blockIdx.y * 128;
  const int n0  = blockIdx.x * 128;

  // global load mapping: each thread loads one float4 of A tile, one of B tile
  const int lr = tid >> 1;               // row within tile 0..127
  const int lc = (tid & 1) << 2;         // col 0 or 4
  const float* Ag = A  + (size_t)(m0 + lr) * K + lc;
  const float* Bg = Bm + (size_t)(n0 + lr) * K + lc;

  float acc[8][8];
  #pragma unroll
  for (int i = 0; i < 8; i++)
    #pragma unroll
    for (int j = 0; j < 8; j++) acc[i][j] = 0.0f;

  for (int k0 = 0; k0 < K; k0 += 8) {
    float4 av = *(const float4*)(Ag + k0);
    float4 bv = *(const float4*)(Bg + k0);
    __syncthreads();
    As[lc+0][lr] = av.x; As[lc+1][lr] = av.y; As[lc+2][lr] = av.z; As[lc+3][lr] = av.w;
    Bs[lc+0][lr] = bv.x; Bs[lc+1][lr] = bv.y; Bs[lc+2][lr] = bv.z; Bs[lc+3][lr] = bv.w;
    __syncthreads();

    #pragma unroll
    for (int k = 0; k < 8; k++) {
      float4 a0 = *(const float4*)&As[k][ty*8];
      float4 a1 = *(const float4*)&As[k][ty*8+4];
      float4 b0 = *(const float4*)&Bs[k][tx*8];
      float4 b1 = *(const float4*)&Bs[k][tx*8+4];
      float ar[8] = {a0.x,a0.y,a0.z,a0.w,a1.x,a1.y,a1.z,a1.w};
      float br[8] = {b0.x,b0.y,b0.z,b0.w,b1.x,b1.y,b1.z,b1.w};
      #pragma unroll
      for (int i = 0; i < 8; i++)
        #pragma unroll
        for (int j = 0; j < 8; j++)
          acc[i][j] += ar[i] * br[j];
    }
  }

  #pragma unroll
  for (int i = 0; i < 8; i++) {
    int m = m0 + ty*8 + i;
    #pragma unroll
    for (int j = 0; j < 8; j += 4) {
      int n = n0 + tx*8 + j;
      float4 v;
      v.x = acc[i][j+0] + bias[n+0];
      v.y = acc[i][j+1] + bias[n+1];
      v.z = acc[i][j+2] + bias[n+2];
      v.w = acc[i][j+3] + bias[n+3];
      *(float4*)(C + (size_t)m * N + n) = v;
    }
  }
}

// ---------------------------------------------------------------------------
// Flash attention (causal, fp32 online softmax).
// Grid: (SEQ/64, B*H).  128 threads: tx = tid&7 (8 col groups), ty = tid>>3
// (16 row groups). Each thread owns 4 q-rows x 8 columns (cols strided:
// c = tx + 8*j so hot smem loads are conflict-free).
// Smem: Qt[d][r] stride 65, Kt[d][c] stride 65, Vs[k][d] stride 64,
//       Ps[r][k] stride 65.
// ---------------------------------------------------------------------------
#define FS_QT 0
#define FS_KT (64*65)
#define FS_VS (2*64*65)
#define FS_PS (2*64*65 + 64*64)
#define FS_TOTAL (2*64*65 + 64*64 + 64*65)   /* 16576 floats = 66304 B */

__global__ __launch_bounds__(128) void flash_kernel(
    const float* __restrict__ qkv, float* __restrict__ out)
{
  extern __shared__ float sm[];
  float* Qt = sm + FS_QT;
  float* Kt = sm + FS_KT;
  float* Vs = sm + FS_VS;
  float* Ps = sm + FS_PS;

  const int tid = threadIdx.x;
  const int tx = tid & 7;
  const int ty = tid >> 3;
  const int qb = blockIdx.x;
  const int bh = blockIdx.y;
  const int b  = bh >> 4;
  const int h  = bh & 15;
  const int q0 = qb * 64;

  const float* qbase = qkv + ((size_t)b * SEQ + q0) * QKVF + h * HDIM;
  const float* kbase = qkv + ((size_t)b * SEQ) * QKVF + EMBED + h * HDIM;
  const float* vbase = kbase + EMBED;

  // Load Q tile (scaled by 1/sqrt(D) = 0.125), store d-major.
  #pragma unroll
  for (int e = tid; e < 64*64; e += 128) {
    int r = e >> 6, d = e & 63;
    Qt[d*65 + r] = qbase[(size_t)r * QKVF + d] * 0.125f;
  }

  float m_i[4], l_i[4], o[4][8];
  #pragma unroll
  for (int i = 0; i < 4; i++) {
    m_i[i] = -1e30f; l_i[i] = 0.0f;
    #pragma unroll
    for (int j = 0; j < 8; j++) o[i][j] = 0.0f;
  }

  for (int kv = 0; kv <= qb; kv++) {
    const int k0 = kv * 64;
    __syncthreads();   // previous iteration's Ps/Vs reads must be done
    #pragma unroll
    for (int e = tid; e < 64*64; e += 128) {
      int r = e >> 6, d = e & 63;
      float kval = kbase[(size_t)(k0 + r) * QKVF + d];
      float vval = vbase[(size_t)(k0 + r) * QKVF + d];
      Kt[d*65 + r] = kval;
      Vs[r*64 + d] = vval;
    }
    __syncthreads();

    // S = Q @ K^T  (outer product over d)
    float s[4][8];
    #pragma unroll
    for (int i = 0; i < 4; i++)
      #pragma unroll
      for (int j = 0; j < 8; j++) s[i][j] = 0.0f;

    #pragma unroll 4
    for (int d = 0; d < 64; d++) {
      float qf[4], kf[8];
      #pragma unroll
      for (int i = 0; i < 4; i++) qf[i] = Qt[d*65 + ty*4 + i];
      #pragma unroll
      for (int j = 0; j < 8; j++) kf[j] = Kt[d*65 + tx + 8*j];
      #pragma unroll
      for (int i = 0; i < 4; i++)
        #pragma unroll
        for (int j = 0; j < 8; j++)
          s[i][j] += qf[i] * kf[j];
    }

    // Causal mask + online softmax update
    const bool diag = (kv == qb);
    #pragma unroll
    for (int i = 0; i < 4; i++) {
      int qg = q0 + ty*4 + i;
      float mx = -1e30f;
      #pragma unroll
      for (int j = 0; j < 8; j++) {
        if (diag && (k0 + tx + 8*j) > qg) s[i][j] = -1e30f;
        mx = fmaxf(mx, s[i][j]);
      }
      mx = fmaxf(mx, __shfl_xor_sync(0xffffffffu, mx, 1));
      mx = fmaxf(mx, __shfl_xor_sync(0xffffffffu, mx, 2));
      mx = fmaxf(mx, __shfl_xor_sync(0xffffffffu, mx, 4));
      float mnew  = fmaxf(m_i[i], mx);
      float alpha = __expf(m_i[i] - mnew);
      m_i[i] = mnew;
      float rs = 0.0f;
      #pragma unroll
      for (int j = 0; j < 8; j++) {
        s[i][j] = __expf(s[i][j] - mnew);
        rs += s[i][j];
      }
      rs += __shfl_xor_sync(0xffffffffu, rs, 1);
      rs += __shfl_xor_sync(0xffffffffu, rs, 2);
      rs += __shfl_xor_sync(0xffffffffu, rs, 4);
      l_i[i] = l_i[i] * alpha + rs;
      #pragma unroll
      for (int j = 0; j < 8; j++) o[i][j] *= alpha;
    }

    // P to smem
    #pragma unroll
    for (int i = 0; i < 4; i++)
      #pragma unroll
      for (int j = 0; j < 8; j++)
        Ps[(ty*4 + i)*65 + tx + 8*j] = s[i][j];
    __syncthreads();

    // O += P @ V
    #pragma unroll 4
    for (int k = 0; k < 64; k++) {
      float pf[4], vf[8];
      #pragma unroll
      for (int i = 0; i < 4; i++) pf[i] = Ps[(ty*4 + i)*65 + k];
      #pragma unroll
      for (int j = 0; j < 8; j++) vf[j] = Vs[k*64 + tx + 8*j];
      #pragma unroll
      for (int i = 0; i < 4; i++)
        #pragma unroll
        for (int j = 0; j < 8; j++)
          o[i][j] += pf[i] * vf[j];
    }
  }

  // Epilogue: normalize and write to [B,T,C] layout (c = h*64 + d)
  #pragma unroll
  for (int i = 0; i < 4; i++) {
    float inv = 1.0f / l_i[i];
    int r = q0 + ty*4 + i;
    float* orow = out + ((size_t)b * SEQ + r) * EMBED + h * HDIM;
    #pragma unroll
    for (int j = 0; j < 8; j++)
      orow[tx + 8*j] = o[i][j] * inv;
  }
}

// ---------------------------------------------------------------------------
extern "C" void kernel_launch(void* const* d_in, const int* in_sizes, int n_in,
                              void* d_out, int out_size)
{
  (void)in_sizes; (void)n_in; (void)out_size;
  const float* x     = (const float*)d_in[0];
  const float* qkv_w = (const float*)d_in[1];
  const float* qkv_b = (const float*)d_in[2];
  const float* out_w = (const float*)d_in[3];
  const float* out_b = (const float*)d_in[4];
  float* y = (float*)d_out;

  float *qkv = nullptr, *att = nullptr;
  cudaGetSymbolAddress((void**)&qkv, g_qkv);
  cudaGetSymbolAddress((void**)&att, g_att);

  cudaFuncSetAttribute(flash_kernel,
                       cudaFuncAttributeMaxDynamicSharedMemorySize,
                       FS_TOTAL * (int)sizeof(float));

  // 1) QKV projection: [8192,1024] @ [3072,1024]^T + b
  sgemm_bias<<<dim3(QKVF/128, MTOT/128), 256>>>(x, qkv_w, qkv_b, qkv,
                                                MTOT, QKVF, EMBED);
  // 2) Causal flash attention
  flash_kernel<<<dim3(SEQ/64, BATCH*NHEAD), 128, FS_TOTAL*(int)sizeof(float)>>>(qkv, att);
  // 3) Output projection: [8192,1024] @ [1024,1024]^T + b
  sgemm_bias<<<dim3(EMBED/128, MTOT/128), 256>>>(att, out_w, out_b, y,
                                                 MTOT, EMBED, EMBED);
}